// round 1
// baseline (speedup 1.0000x reference)
#include <cuda_runtime.h>

#define NT    256      // threads per block
#define LSEQ  8192     // sequence length
#define KB    8        // kernel count per group (K)
#define CIN   12       // input channels
#define CPER  6        // gathered channels per group (C_IN_PER)
#define NG    32       // groups (_G)
#define NDIL  10       // dilations

// Output: (32, 4*NDIL*NG, KB) = (32, 1280, 8) fp32
// Block = one (b, di, j, g). Stages gather-summed input (+halo) in shared,
// runs the 9-tap dilated conv for all 8 kernels, tracks max/argmax/argmin,
// accumulates per-thread histograms in shared, reduces, writes 16 outputs.

__global__ __launch_bounds__(NT) void hydra_kernel(
    const float* __restrict__ X,   // (32, 12, 8192)
    const float* __restrict__ W,   // (10, 2, 256, 1, 9)
    const int*   __restrict__ I,   // (10, 2, 32, 6)
    float* __restrict__ out,       // (32, 1280, 8)
    int di, int d)
{
    extern __shared__ float smem[];
    float* accum = smem;                 // 16 * NT floats (per-thread histogram slots)
    float* wsh   = smem + 16 * NT;       // 72 floats (weights for this (dj,g))
    float* inp   = wsh + 72;             // S+1 floats (staged gather-sum with halo)

    const int g   = blockIdx.x;
    const int jj  = blockIdx.y;          // 0 = X branch, 1 = diff branch
    const int b   = blockIdx.z;
    const int tid = threadIdx.x;

    const int dj = di * 2 + jj;
    const int S  = LSEQ + 8 * d;         // slots: slot s <-> t = s - 4d

    // ---- weights to shared (one block-wide copy) ----
    if (tid < KB * 9)
        wsh[tid] = W[(dj * NG * KB + g * KB) * 9 + tid];

    // ---- zero histogram slots ----
#pragma unroll
    for (int q = 0; q < 16; q++) accum[q * NT + tid] = 0.f;

    // ---- gather indices for this (dj, g) ----
    int idx[CPER];
#pragma unroll
    for (int c = 0; c < CPER; c++)
        idx[c] = I[(dj * NG + g) * CPER + c] * LSEQ;

    const float* Xb = X + (size_t)b * CIN * LSEQ;

    // ---- stage gather-sum into shared (S+1 slots; slot S needed for diff) ----
    for (int s = tid; s < S + 1; s += NT) {
        int t = s - 4 * d;
        float v = 0.f;
        if (t >= 0 && t < LSEQ) {
#pragma unroll
            for (int c = 0; c < CPER; c++) v += Xb[idx[c] + t];
        }
        inp[s] = v;
    }
    __syncthreads();

    // ---- diff branch: in-place chunked diff (diff is linear over the gather-sum) ----
    if (jj == 1) {
        for (int base = 0; base < S; base += NT) {
            int s = base + tid;
            float dv = 0.f;
            if (s < S) {
                int t = s - 4 * d;
                float a  = inp[s];
                float b2 = inp[s + 1];
                if (t >= 0 && t < LSEQ - 1) dv = b2 - a;
            }
            __syncthreads();           // all reads of this chunk done
            if (s < S) inp[s] = dv;
            __syncthreads();           // writes visible before next chunk reads
        }
    }

    // ---- weights to registers ----
    float w[KB][9];
#pragma unroll
    for (int k = 0; k < KB; k++)
#pragma unroll
        for (int i = 0; i < 9; i++) w[k][i] = wsh[k * 9 + i];

    // ---- main conv + max/argmax/argmin + histogram ----
    const int Lj = LSEQ - jj;           // 8192 (j=0) or 8191 (j=1)
    for (int t = tid; t < Lj; t += NT) {
        float x[9];
#pragma unroll
        for (int i = 0; i < 9; i++) x[i] = inp[t + i * d];  // tap i at t+(i-4)d

        float maxv = 0.f, minv = 0.f;
        int   maxi = 0,   mini = 0;
#pragma unroll
        for (int k = 0; k < KB; k++) {
            float z = w[k][0] * x[0];
#pragma unroll
            for (int i = 1; i < 9; i++) z = fmaf(w[k][i], x[i], z);
            if (k == 0) {
                maxv = z; minv = z; maxi = 0; mini = 0;
            } else {
                if (z > maxv) { maxv = z; maxi = k; }   // first-occurrence argmax
                if (z < minv) { minv = z; mini = k; }   // first-occurrence argmin
            }
        }
        accum[maxi * NT + tid]      += maxv;   // bank = tid%32: conflict-free
        accum[(8 + mini) * NT + tid] += 1.0f;
    }
    __syncthreads();

    // ---- block reduction over the 256 per-thread slots, all 16 bins ----
    for (int stride = NT / 2; stride > 0; stride >>= 1) {
        if (tid < stride) {
#pragma unroll
            for (int q = 0; q < 16; q++)
                accum[q * NT + tid] += accum[q * NT + tid + stride];
        }
        __syncthreads();
    }

    // ---- write 16 outputs: ch = (di*4 + j*2 + which)*NG + g, with relu ----
    if (tid < 16) {
        int which = tid >> 3;
        int k     = tid & 7;
        float v = fmaxf(accum[tid * NT], 0.f);
        size_t ch = (size_t)((di * 4 + jj * 2 + which) * NG + g);
        out[((size_t)b * (4 * NDIL * NG) + ch) * KB + k] = v;
    }
}

extern "C" void kernel_launch(void* const* d_in, const int* in_sizes, int n_in,
                              void* d_out, int out_size) {
    const float* X = (const float*)d_in[0];
    const float* W = (const float*)d_in[1];
    const int*   I = (const int*)d_in[2];
    float* out = (float*)d_out;

    // worst-case dynamic smem (d = 512)
    int maxbytes = (16 * NT + 72 + (LSEQ + 8 * 512 + 2)) * (int)sizeof(float);
    cudaFuncSetAttribute(hydra_kernel,
                         cudaFuncAttributeMaxDynamicSharedMemorySize, maxbytes);

    for (int di = 0; di < NDIL; di++) {
        int d = 1 << di;
        int smem = (16 * NT + 72 + (LSEQ + 8 * d + 2)) * (int)sizeof(float);
        dim3 grid(NG, 2, 32);   // (g, j, b)
        hydra_kernel<<<grid, NT, smem>>>(X, W, I, out, di, d);
    }
}

// round 4
// speedup vs baseline: 1.3458x; 1.3458x over previous
#include <cuda_runtime.h>

#define NT    256      // threads per block
#define LSEQ  8192     // sequence length
#define KB    8        // kernels per group
#define CIN   12       // input channels
#define CPER  6        // gathered channels per group
#define NG    32       // groups
#define NDIL  10       // dilations

// packed f32x2 helpers (sm_100+ PTX; ptxas never auto-fuses these)
union F2 { float2 f; unsigned long long u; };

__device__ __forceinline__ void ffma2(F2& d, const F2& a, const F2& b, const F2& c) {
    asm("fma.rn.f32x2 %0, %1, %2, %3;" : "=l"(d.u) : "l"(a.u), "l"(b.u), "l"(c.u));
}
__device__ __forceinline__ void fmul2(F2& d, const F2& a, const F2& b) {
    asm("mul.rn.f32x2 %0, %1, %2;" : "=l"(d.u) : "l"(a.u), "l"(b.u));
}

// Block = one (b, di, j, g). Stages gather-summed input (+halo) in shared,
// 9-tap dilated conv for 8 kernels (k-packed f32x2), max/min via FMNMX tree,
// histogram via equality-predicated register accumulators, shuffle reduce.
template<int D>
__global__ __launch_bounds__(NT) void hydra_kernel(
    const float* __restrict__ X,   // (32, 12, 8192)
    const float* __restrict__ W,   // (10, 2, 256, 1, 9)
    const int*   __restrict__ I,   // (10, 2, 32, 6)
    float* __restrict__ out,       // (32, 1280, 8)
    int di)
{
    extern __shared__ float smem[];
    float* wsh = smem;                   // 72 floats, TRANSPOSED: wsh[i*8 + k]
    float* inp = smem + 72;              // S+1 floats

    const int g   = blockIdx.x;
    const int jj  = blockIdx.y;          // 0 = X branch, 1 = diff branch
    const int b   = blockIdx.z;
    const int tid = threadIdx.x;

    const int dj = di * 2 + jj;
    const int S  = LSEQ + 8 * D;         // slot s <-> t = s - 4D

    // ---- weights to shared, transposed to [tap][k] so (k,k+1) pairs are adjacent ----
    if (tid < KB * 9) {
        int k = tid / 9, i = tid % 9;
        wsh[i * 8 + k] = W[((dj * NG + g) * KB + k) * 9 + i];
    }

    // ---- gather indices ----
    int idx[CPER];
#pragma unroll
    for (int c = 0; c < CPER; c++)
        idx[c] = I[(dj * NG + g) * CPER + c] * LSEQ;

    const float* Xb = X + (size_t)b * CIN * LSEQ;

    // ---- stage gather-sum into shared (S+1 slots) ----
    for (int s = tid; s < S + 1; s += NT) {
        int t = s - 4 * D;
        float v = 0.f;
        if (t >= 0 && t < LSEQ) {
#pragma unroll
            for (int c = 0; c < CPER; c++) v += Xb[idx[c] + t];
        }
        inp[s] = v;
    }
    __syncthreads();

    // ---- diff branch: in-place chunked diff (linear over the gather-sum) ----
    if (jj == 1) {
        for (int base = 0; base < S; base += NT) {
            int s = base + tid;
            float dv = 0.f;
            if (s < S) {
                int t = s - 4 * D;
                float a  = inp[s];
                float b2 = inp[s + 1];
                if (t >= 0 && t < LSEQ - 1) dv = b2 - a;
            }
            __syncthreads();
            if (s < S) inp[s] = dv;
            __syncthreads();
        }
    }

    // ---- weights to packed registers: w2[i][kp] = (w[2kp][i], w[2kp+1][i]) ----
    F2 w2[9][4];
#pragma unroll
    for (int i = 0; i < 9; i++)
#pragma unroll
        for (int kp = 0; kp < 4; kp++)
            w2[i][kp].f = *reinterpret_cast<const float2*>(&wsh[i * 8 + kp * 2]);

    float cmax[KB], cmin[KB];
#pragma unroll
    for (int k = 0; k < KB; k++) { cmax[k] = 0.f; cmin[k] = 0.f; }

    const int Lj = LSEQ - jj;            // 8192 or 8191

    // ---- main loop: exactly LSEQ/NT = 32 iterations ----
#pragma unroll 2
    for (int it = 0; it < LSEQ / NT; it++) {
        const int t = tid + it * NT;
        const float* ip = inp + t;

        F2 z[4];
        F2 xx;
        float xv = ip[0];
        xx.f.x = xv; xx.f.y = xv;
#pragma unroll
        for (int kp = 0; kp < 4; kp++) fmul2(z[kp], w2[0][kp], xx);
#pragma unroll
        for (int i = 1; i < 9; i++) {
            xv = ip[i * D];              // immediate LDS offsets (D compile-time)
            xx.f.x = xv; xx.f.y = xv;
#pragma unroll
            for (int kp = 0; kp < 4; kp++) ffma2(z[kp], w2[i][kp], xx, z[kp]);
        }

        float m0 = fmaxf(z[0].f.x, z[0].f.y);
        float m1 = fmaxf(z[1].f.x, z[1].f.y);
        float m2 = fmaxf(z[2].f.x, z[2].f.y);
        float m3 = fmaxf(z[3].f.x, z[3].f.y);
        float maxv = fmaxf(fmaxf(m0, m1), fmaxf(m2, m3));
        float n0 = fminf(z[0].f.x, z[0].f.y);
        float n1 = fminf(z[1].f.x, z[1].f.y);
        float n2 = fminf(z[2].f.x, z[2].f.y);
        float n3 = fminf(z[3].f.x, z[3].f.y);
        float minv = fminf(fminf(n0, n1), fminf(n2, n3));

        if (t < Lj) {
#pragma unroll
            for (int kp = 0; kp < 4; kp++) {
                float zl = z[kp].f.x, zh = z[kp].f.y;
                if (zl == maxv) cmax[2 * kp]     += zl;
                if (zh == maxv) cmax[2 * kp + 1] += zh;
                if (zl == minv) cmin[2 * kp]     += 1.f;
                if (zh == minv) cmin[2 * kp + 1] += 1.f;
            }
        }
    }

    // ---- warp shuffle reduction of 16 accumulators ----
#pragma unroll
    for (int off = 16; off > 0; off >>= 1) {
#pragma unroll
        for (int k = 0; k < KB; k++) {
            cmax[k] += __shfl_down_sync(0xffffffffu, cmax[k], off);
            cmin[k] += __shfl_down_sync(0xffffffffu, cmin[k], off);
        }
    }

    __syncthreads();                     // inp reads done; reuse as reduction scratch
    float* red = inp;                    // red[q*8 + warp], q in [0,16)
    const int warp = tid >> 5;
    if ((tid & 31) == 0) {
#pragma unroll
        for (int k = 0; k < KB; k++) {
            red[k * 8 + warp]        = cmax[k];
            red[(8 + k) * 8 + warp]  = cmin[k];
        }
    }
    __syncthreads();

    if (tid < 16) {
        float v = 0.f;
#pragma unroll
        for (int w = 0; w < 8; w++) v += red[tid * 8 + w];
        v = fmaxf(v, 0.f);
        int which = tid >> 3;            // 0 = cmax, 1 = cmin
        int k     = tid & 7;
        size_t ch = (size_t)((di * 4 + jj * 2 + which) * NG + g);
        out[((size_t)b * (4 * NDIL * NG) + ch) * KB + k] = v;
    }
}

template<int D>
static void launch_one(const float* X, const float* W, const int* I,
                       float* out, int di) {
    int smem = (72 + LSEQ + 8 * D + 1) * (int)sizeof(float);
    cudaFuncSetAttribute(hydra_kernel<D>,
                         cudaFuncAttributeMaxDynamicSharedMemorySize, smem);
    dim3 grid(NG, 2, 32);                // (g, j, b)
    hydra_kernel<D><<<grid, NT, smem>>>(X, W, I, out, di);
}

extern "C" void kernel_launch(void* const* d_in, const int* in_sizes, int n_in,
                              void* d_out, int out_size) {
    const float* X = (const float*)d_in[0];
    const float* W = (const float*)d_in[1];
    const int*   I = (const int*)d_in[2];
    float* out = (float*)d_out;

    launch_one<1>(X, W, I, out, 0);
    launch_one<2>(X, W, I, out, 1);
    launch_one<4>(X, W, I, out, 2);
    launch_one<8>(X, W, I, out, 3);
    launch_one<16>(X, W, I, out, 4);
    launch_one<32>(X, W, I, out, 5);
    launch_one<64>(X, W, I, out, 6);
    launch_one<128>(X, W, I, out, 7);
    launch_one<256>(X, W, I, out, 8);
    launch_one<512>(X, W, I, out, 9);
}